// round 1
// baseline (speedup 1.0000x reference)
#include <cuda_runtime.h>
#include <math.h>

// Problem dims (fixed by the dataset)
#define BDIM 4
#define TDIM 2048
#define DDIM 512
#define EDIM 4
#define CDIM 1024
#define HEDIM 512
#define ODIM 512
#define ECDIM (EDIM * CDIM)   // 4096

// Scratch intermediates (no cudaMalloc allowed -> __device__ globals)
__device__ float g_xd[(size_t)BDIM * ECDIM * DDIM];   // [B][E*C][D]   33.5 MB
__device__ float g_h [(size_t)BDIM * ECDIM * HEDIM];  // [B][E*C][HE]  33.5 MB
__device__ float g_y [(size_t)BDIM * ECDIM * ODIM];   // [B][E*C][O]   33.5 MB

// Tiled GEMM: C[z] = op(A[z]) * B[z%bMod]  (+ bias, + gelu)
// A_KMAJOR=true : A stored [K][M], row length lda (dispatch mask case)
// A_KMAJOR=false: A stored [M][K], row length lda (standard row-major)
// B always stored [K][N], row length ldb. C row-major [M][N], row length ldc.
template<bool A_KMAJOR, bool GELU, bool HAS_BIAS>
__global__ __launch_bounds__(256, 2)
void gemm_k(const float* __restrict__ Abase, const float* __restrict__ Bbase,
            float* __restrict__ Cbase, const float* __restrict__ biasBase,
            int M, int N, int K, int lda, int ldb, int ldc,
            long long sA, long long sB, long long sC, long long sBias,
            int bMod, int biasMod)
{
    constexpr int BM = 128, BN = 64, BK = 16, TM = 8, TN = 4;
    __shared__ float As[BK][BM];
    __shared__ float Bs[BK][BN];

    const int z = blockIdx.z;
    const float* A = Abase + (long long)z * sA;
    const float* B = Bbase + (long long)(bMod ? (z % bMod) : z) * sB;
    float* C = Cbase + (long long)z * sC;
    const float* bias = nullptr;
    if (HAS_BIAS)
        bias = biasBase + (long long)(biasMod ? (z % biasMod) : z) * sBias;

    const int m0 = blockIdx.y * BM;
    const int n0 = blockIdx.x * BN;
    const int tid = threadIdx.x;
    const int ty = tid >> 4;   // 0..15 -> M direction
    const int tx = tid & 15;   // 0..15 -> N direction

    float acc[TM][TN];
#pragma unroll
    for (int i = 0; i < TM; i++)
#pragma unroll
        for (int j = 0; j < TN; j++) acc[i][j] = 0.f;

    for (int k0 = 0; k0 < K; k0 += BK) {
        // ---- load A tile into As[k][m] ----
        if (A_KMAJOR) {
            // A[k][m]: coalesced along m, direct float4 copy
            const int k  = tid >> 5;   // 0..7
            const int m4 = tid & 31;   // 0..31 -> 4 floats each
#pragma unroll
            for (int it = 0; it < 2; ++it) {
                const int kk = k + it * 8;
                float4 v = *reinterpret_cast<const float4*>(
                    A + (long long)(k0 + kk) * lda + m0 + m4 * 4);
                *reinterpret_cast<float4*>(&As[kk][m4 * 4]) = v;
            }
        } else {
            // A[m][k]: float4 along k, transpose into As
            const int m    = tid >> 1;  // 0..127
            const int half = tid & 1;   // 0/1
#pragma unroll
            for (int it = 0; it < 2; ++it) {
                const int kv = half * 2 + it;  // 0..3 (float4 index)
                float4 v = *reinterpret_cast<const float4*>(
                    A + (long long)(m0 + m) * lda + k0 + kv * 4);
                As[kv * 4 + 0][m] = v.x;
                As[kv * 4 + 1][m] = v.y;
                As[kv * 4 + 2][m] = v.z;
                As[kv * 4 + 3][m] = v.w;
            }
        }
        // ---- load B tile [BK][BN] ----
        {
            const int k  = tid >> 4;   // 0..15
            const int n4 = tid & 15;   // 0..15
            float4 v = *reinterpret_cast<const float4*>(
                B + (long long)(k0 + k) * ldb + n0 + n4 * 4);
            *reinterpret_cast<float4*>(&Bs[k][n4 * 4]) = v;
        }
        __syncthreads();

#pragma unroll
        for (int kk = 0; kk < BK; ++kk) {
            float a[TM], b[TN];
            float4 a0 = *reinterpret_cast<const float4*>(&As[kk][ty * TM]);
            float4 a1 = *reinterpret_cast<const float4*>(&As[kk][ty * TM + 4]);
            a[0] = a0.x; a[1] = a0.y; a[2] = a0.z; a[3] = a0.w;
            a[4] = a1.x; a[5] = a1.y; a[6] = a1.z; a[7] = a1.w;
            float4 b0 = *reinterpret_cast<const float4*>(&Bs[kk][tx * TN]);
            b[0] = b0.x; b[1] = b0.y; b[2] = b0.z; b[3] = b0.w;
#pragma unroll
            for (int i = 0; i < TM; i++)
#pragma unroll
                for (int j = 0; j < TN; j++)
                    acc[i][j] = fmaf(a[i], b[j], acc[i][j]);
        }
        __syncthreads();
    }

    // ---- epilogue: bias, gelu, vectorized store ----
#pragma unroll
    for (int i = 0; i < TM; i++) {
        const int row = m0 + ty * TM + i;
        float v[TN];
#pragma unroll
        for (int j = 0; j < TN; j++) {
            const int col = n0 + tx * TN + j;
            float t = acc[i][j];
            if (HAS_BIAS) t += bias[col];
            if (GELU) t = 0.5f * t * (1.0f + erff(t * 0.70710678118654752f));
            v[j] = t;
        }
        float4 o = make_float4(v[0], v[1], v[2], v[3]);
        *reinterpret_cast<float4*>(C + (long long)row * ldc + n0 + tx * TN) = o;
    }
}

extern "C" void kernel_launch(void* const* d_in, const int* in_sizes, int n_in,
                              void* d_out, int out_size)
{
    const float* x     = (const float*)d_in[0];  // [B,T,D]
    const float* dmask = (const float*)d_in[1];  // [B,T,E,C]
    const float* comb  = (const float*)d_in[2];  // [B,T,E,C]
    const float* w1    = (const float*)d_in[3];  // [E,D,HE]
    const float* b1    = (const float*)d_in[4];  // [E,HE]
    const float* w2    = (const float*)d_in[5];  // [E,HE,O]
    const float* b2    = (const float*)d_in[6];  // [O]
    float* out = (float*)d_out;                  // [B,T,O]

    float *xd, *h, *y;
    cudaGetSymbolAddress((void**)&xd, g_xd);
    cudaGetSymbolAddress((void**)&h,  g_h);
    cudaGetSymbolAddress((void**)&y,  g_y);

    const dim3 blk(256);

    // K1: dispatch  xd_b[EC,D] = dmask_b^T[EC,T] * x_b[T,D]
    // A stored [K=T][M=EC] (K-major), B = x [K=T][N=D]
    gemm_k<true, false, false><<<dim3(DDIM / 64, ECDIM / 128, BDIM), blk>>>(
        dmask, x, xd, nullptr,
        ECDIM, DDIM, TDIM, /*lda*/ ECDIM, /*ldb*/ DDIM, /*ldc*/ DDIM,
        (long long)TDIM * ECDIM, (long long)TDIM * DDIM, (long long)ECDIM * DDIM, 0,
        0, 0);

    // K2: fc1 + bias + gelu   h_{b,e}[C,HE] = gelu(xd_{b,e}[C,D] * w1_e[D,HE] + b1_e)
    gemm_k<false, true, true><<<dim3(HEDIM / 64, CDIM / 128, BDIM * EDIM), blk>>>(
        xd, w1, h, b1,
        CDIM, HEDIM, DDIM, /*lda*/ DDIM, /*ldb*/ HEDIM, /*ldc*/ HEDIM,
        (long long)CDIM * DDIM, (long long)DDIM * HEDIM, (long long)CDIM * HEDIM,
        (long long)HEDIM,
        EDIM, EDIM);

    // K3: fc2   y_{b,e}[C,O] = h_{b,e}[C,HE] * w2_e[HE,O]
    gemm_k<false, false, false><<<dim3(ODIM / 64, CDIM / 128, BDIM * EDIM), blk>>>(
        h, w2, y, nullptr,
        CDIM, ODIM, HEDIM, /*lda*/ HEDIM, /*ldb*/ ODIM, /*ldc*/ ODIM,
        (long long)CDIM * HEDIM, (long long)HEDIM * ODIM, (long long)CDIM * ODIM, 0,
        EDIM, 0);

    // K4: combine + b2   out_b[T,O] = comb_b[T,EC] * y_b[EC,O] + b2
    gemm_k<false, false, true><<<dim3(ODIM / 64, TDIM / 128, BDIM), blk>>>(
        comb, y, out, b2,
        TDIM, ODIM, ECDIM, /*lda*/ ECDIM, /*ldb*/ ODIM, /*ldc*/ ODIM,
        (long long)TDIM * ECDIM, (long long)ECDIM * ODIM, (long long)TDIM * ODIM, 0,
        0, 1);
}

// round 3
// speedup vs baseline: 2.6288x; 2.6288x over previous
#include <cuda_runtime.h>
#include <cuda_bf16.h>
#include <math.h>
#include <stdint.h>

// ---------------- problem dims ----------------
#define BDIM 4
#define TDIM 2048
#define DDIM 512
#define EDIM 4
#define CDIM 1024
#define HEDIM 512
#define ODIM 512
#define ECDIM 4096

// scratch intermediates (no cudaMalloc allowed)
__device__ float g_xd[(size_t)BDIM * ECDIM * DDIM];
__device__ float g_h [(size_t)BDIM * ECDIM * HEDIM];
__device__ float g_y [(size_t)BDIM * ECDIM * ODIM];

// ---------------- tile config ----------------
constexpr int BM = 128, BN = 128, BK = 32;
constexpr int THREADS = 256;
// stage layout (bytes): A_hi[128][64B] A_lo B_hi[32][256B] B_lo
constexpr int OFF_AHI = 0;
constexpr int OFF_ALO = 8192;
constexpr int OFF_BHI = 16384;
constexpr int OFF_BLO = 24576;
constexpr int STAGE   = 32768;
constexpr int SMEM_TOTAL = 2 * STAGE;   // 64 KB

// smem offsets with bank-conflict-avoiding XOR swizzles
__device__ __forceinline__ int a_off(int m, int kchunk) {  // kchunk 0..3 (8 bf16 each)
    return m * 64 + ((kchunk ^ ((m >> 1) & 3)) << 4);
}
__device__ __forceinline__ int b_off(int k, int nchunk) {  // nchunk 0..15
    return k * 256 + ((nchunk ^ (k & 7)) << 4);
}

__device__ __forceinline__ uint32_t smem_u32(const void* p) {
    uint32_t a;
    asm("{ .reg .u64 t; cvta.to.shared.u64 t, %1; cvt.u32.u64 %0, t; }"
        : "=r"(a) : "l"(p));
    return a;
}
__device__ __forceinline__ void ldsm4(uint32_t* r, uint32_t addr) {
    asm volatile("ldmatrix.sync.aligned.m8n8.x4.shared.b16 {%0,%1,%2,%3}, [%4];"
                 : "=r"(r[0]), "=r"(r[1]), "=r"(r[2]), "=r"(r[3]) : "r"(addr));
}
__device__ __forceinline__ void ldsm4t(uint32_t* r, uint32_t addr) {
    asm volatile("ldmatrix.sync.aligned.m8n8.x4.trans.shared.b16 {%0,%1,%2,%3}, [%4];"
                 : "=r"(r[0]), "=r"(r[1]), "=r"(r[2]), "=r"(r[3]) : "r"(addr));
}
__device__ __forceinline__ void mma_bf16(float* d, const uint32_t* a, const uint32_t* b) {
    asm volatile(
        "mma.sync.aligned.m16n8k16.row.col.f32.bf16.bf16.f32 "
        "{%0,%1,%2,%3}, {%4,%5,%6,%7}, {%8,%9}, {%0,%1,%2,%3};"
        : "+f"(d[0]), "+f"(d[1]), "+f"(d[2]), "+f"(d[3])
        : "r"(a[0]), "r"(a[1]), "r"(a[2]), "r"(a[3]), "r"(b[0]), "r"(b[1]));
}

// fp32 -> (hi bf16 truncated, lo = rn(x-hi)) for 4 elems packed as uint2
__device__ __forceinline__ void split4(const float4& v, uint2& h, uint2& l) {
    uint32_t ax = __float_as_uint(v.x), ay = __float_as_uint(v.y);
    uint32_t az = __float_as_uint(v.z), aw = __float_as_uint(v.w);
    h.x = (ax >> 16) | (ay & 0xffff0000u);
    h.y = (az >> 16) | (aw & 0xffff0000u);
    float lx = v.x - __uint_as_float(ax & 0xffff0000u);
    float ly = v.y - __uint_as_float(ay & 0xffff0000u);
    float lz = v.z - __uint_as_float(az & 0xffff0000u);
    float lw = v.w - __uint_as_float(aw & 0xffff0000u);
    __nv_bfloat162 p0 = __floats2bfloat162_rn(lx, ly);
    __nv_bfloat162 p1 = __floats2bfloat162_rn(lz, lw);
    l.x = *reinterpret_cast<uint32_t*>(&p0);
    l.y = *reinterpret_cast<uint32_t*>(&p1);
}

// ---------------- main GEMM kernel ----------------
// C[z](MxN) = op(A[z]) * B[z or z%bMod] (+bias)(gelu)
// AT=false: A row-major [m][k] stride lda.  AT=true: A stored [k][m] stride lda.
// B row-major [k][n] stride ldb.
template<bool AT, bool GELU_, bool BIAS_>
__global__ __launch_bounds__(THREADS, 1)
void moe_gemm(const float* __restrict__ Abase, const float* __restrict__ Bbase,
              float* __restrict__ Cbase, const float* __restrict__ biasBase,
              int lda, int ldb, int ldc, int KT,
              long long sA, long long sB, long long sC, int bMod,
              long long sBias, int biasMod)
{
    extern __shared__ char smem[];
    const int tid  = threadIdx.x;
    const int lane = tid & 31;
    const int wid  = tid >> 5;
    const int wm   = (wid & 1) * 64;   // warp m offset
    const int wn   = (wid >> 1) * 32;  // warp n offset

    const int z = blockIdx.z;
    const float* A = Abase + (long long)z * sA;
    const float* B = Bbase + (long long)(bMod ? (z % bMod) : z) * sB;
    float* C = Cbase + (long long)z * sC;
    const float* bias = BIAS_
        ? biasBase + (long long)(biasMod ? (z % biasMod) : z) * sBias : nullptr;

    const int m0 = blockIdx.y * BM;
    const int n0 = blockIdx.x * BN;

    const uint32_t sbase = smem_u32(smem);

    float acc[4][4][4];
#pragma unroll
    for (int i = 0; i < 4; i++)
#pragma unroll
        for (int j = 0; j < 4; j++)
#pragma unroll
            for (int c = 0; c < 4; c++) acc[i][j][c] = 0.f;

    float4 ra[4], rb[4];

    // ---- global load of one k-tile into registers ----
    auto loadA = [&](int k0g) {
#pragma unroll
        for (int i = 0; i < 4; i++) {
            int idx = tid + i * THREADS;
            if (AT) {
                int kq = idx >> 7, m = idx & 127;
                const float* p = A + (size_t)(k0g + kq * 4) * lda + m0 + m;
                ra[i].x = p[0]; ra[i].y = p[lda];
                ra[i].z = p[2 * lda]; ra[i].w = p[3 * lda];
            } else {
                int m = idx >> 3, kq = idx & 7;
                ra[i] = *reinterpret_cast<const float4*>(
                    A + (size_t)(m0 + m) * lda + k0g + kq * 4);
            }
        }
#pragma unroll
        for (int i = 0; i < 4; i++) {
            int idx = tid + i * THREADS;
            int k = idx >> 5, nq = idx & 31;
            rb[i] = *reinterpret_cast<const float4*>(
                B + (size_t)(k0g + k) * ldb + n0 + nq * 4);
        }
    };
    // ---- split + store registers into smem stage ----
    auto storeS = [&](char* st) {
#pragma unroll
        for (int i = 0; i < 4; i++) {
            int idx = tid + i * THREADS;
            int m, kq;
            if (AT) { kq = (idx >> 7) * 2; m = idx & 127; kq = (idx >> 7); }
            // recompute cleanly below
            if (AT) { kq = idx >> 7; m = idx & 127; }
            else    { m = idx >> 3;  kq = idx & 7; }
            uint2 h, l; split4(ra[i], h, l);
            int off = a_off(m, kq >> 1) + (kq & 1) * 8;
            *reinterpret_cast<uint2*>(st + OFF_AHI + off) = h;
            *reinterpret_cast<uint2*>(st + OFF_ALO + off) = l;
        }
#pragma unroll
        for (int i = 0; i < 4; i++) {
            int idx = tid + i * THREADS;
            int k = idx >> 5, nq = idx & 31;
            uint2 h, l; split4(rb[i], h, l);
            int off = b_off(k, nq >> 1) + (nq & 1) * 8;
            *reinterpret_cast<uint2*>(st + OFF_BHI + off) = h;
            *reinterpret_cast<uint2*>(st + OFF_BLO + off) = l;
        }
    };

    // prologue: tile 0
    loadA(0);
    storeS(smem);
    __syncthreads();

    for (int it = 0; it < KT; ++it) {
        const uint32_t cur = sbase + (it & 1) * STAGE;
        char* nxt = smem + ((it + 1) & 1) * STAGE;
        const bool more = (it + 1 < KT);
        if (more) loadA((it + 1) * BK);

#pragma unroll
        for (int kh = 0; kh < 2; kh++) {
            uint32_t ah[4][4], al[4][4];
#pragma unroll
            for (int mf = 0; mf < 4; mf++) {
                int row = wm + mf * 16 + (lane & 15);
                int chunk = kh * 2 + (lane >> 4);
                int off = a_off(row, chunk);
                ldsm4(ah[mf], cur + OFF_AHI + off);
                ldsm4(al[mf], cur + OFF_ALO + off);
            }
            uint32_t bh[2][4], bl[2][4];
#pragma unroll
            for (int half = 0; half < 2; half++) {
                int k = kh * 16 + ((lane >> 3) & 1) * 8 + (lane & 7);
                int nchunk = ((wn + half * 16) >> 3) + (lane >> 4);
                int off = b_off(k, nchunk);
                ldsm4t(bh[half], cur + OFF_BHI + off);
                ldsm4t(bl[half], cur + OFF_BLO + off);
            }
#pragma unroll
            for (int mf = 0; mf < 4; mf++)
#pragma unroll
                for (int nf = 0; nf < 4; nf++) {
                    const uint32_t* bhf = &bh[nf >> 1][(nf & 1) * 2];
                    const uint32_t* blf = &bl[nf >> 1][(nf & 1) * 2];
                    mma_bf16(acc[mf][nf], ah[mf], bhf);
                    mma_bf16(acc[mf][nf], ah[mf], blf);
                    mma_bf16(acc[mf][nf], al[mf], bhf);
                }
        }

        if (more) storeS(nxt);
        __syncthreads();
    }

    // ---- epilogue ----
    const int g = lane >> 2, t = lane & 3;
#pragma unroll
    for (int mf = 0; mf < 4; mf++) {
#pragma unroll
        for (int nf = 0; nf < 4; nf++) {
            int row = m0 + wm + mf * 16 + g;
            int col = n0 + wn + nf * 8 + t * 2;
            float v0 = acc[mf][nf][0], v1 = acc[mf][nf][1];
            float v2 = acc[mf][nf][2], v3 = acc[mf][nf][3];
            if (BIAS_) {
                float2 bv = *reinterpret_cast<const float2*>(bias + col);
                v0 += bv.x; v1 += bv.y; v2 += bv.x; v3 += bv.y;
            }
            if (GELU_) {
                v0 = 0.5f * v0 * (1.0f + erff(v0 * 0.70710678118654752f));
                v1 = 0.5f * v1 * (1.0f + erff(v1 * 0.70710678118654752f));
                v2 = 0.5f * v2 * (1.0f + erff(v2 * 0.70710678118654752f));
                v3 = 0.5f * v3 * (1.0f + erff(v3 * 0.70710678118654752f));
            }
            *reinterpret_cast<float2*>(C + (size_t)row * ldc + col) =
                make_float2(v0, v1);
            *reinterpret_cast<float2*>(C + (size_t)(row + 8) * ldc + col) =
                make_float2(v2, v3);
        }
    }
}

// ---------------- launcher ----------------
extern "C" void kernel_launch(void* const* d_in, const int* in_sizes, int n_in,
                              void* d_out, int out_size)
{
    const float* x     = (const float*)d_in[0];  // [B,T,D]
    const float* dmask = (const float*)d_in[1];  // [B,T,E,C]
    const float* comb  = (const float*)d_in[2];  // [B,T,E,C]
    const float* w1    = (const float*)d_in[3];  // [E,D,HE]
    const float* b1    = (const float*)d_in[4];  // [E,HE]
    const float* w2    = (const float*)d_in[5];  // [E,HE,O]
    const float* b2    = (const float*)d_in[6];  // [O]
    float* out = (float*)d_out;                  // [B,T,O]

    float *xd, *h, *y;
    cudaGetSymbolAddress((void**)&xd, g_xd);
    cudaGetSymbolAddress((void**)&h,  g_h);
    cudaGetSymbolAddress((void**)&y,  g_y);

    cudaFuncSetAttribute(moe_gemm<true,  false, false>,
                         cudaFuncAttributeMaxDynamicSharedMemorySize, SMEM_TOTAL);
    cudaFuncSetAttribute(moe_gemm<false, true,  true>,
                         cudaFuncAttributeMaxDynamicSharedMemorySize, SMEM_TOTAL);
    cudaFuncSetAttribute(moe_gemm<false, false, false>,
                         cudaFuncAttributeMaxDynamicSharedMemorySize, SMEM_TOTAL);
    cudaFuncSetAttribute(moe_gemm<false, false, true>,
                         cudaFuncAttributeMaxDynamicSharedMemorySize, SMEM_TOTAL);

    // K1: xd_b[EC,D] = dmask_b^T * x_b
    moe_gemm<true, false, false>
        <<<dim3(DDIM / BN, ECDIM / BM, BDIM), THREADS, SMEM_TOTAL>>>(
        dmask, x, xd, nullptr,
        ECDIM, DDIM, DDIM, TDIM / BK,
        (long long)TDIM * ECDIM, (long long)TDIM * DDIM, (long long)ECDIM * DDIM,
        0, 0, 0);

    // K2: h_{b,e}[C,HE] = gelu(xd_{b,e}[C,D] * w1_e + b1_e)
    moe_gemm<false, true, true>
        <<<dim3(HEDIM / BN, CDIM / BM, BDIM * EDIM), THREADS, SMEM_TOTAL>>>(
        xd, w1, h, b1,
        DDIM, HEDIM, HEDIM, DDIM / BK,
        (long long)CDIM * DDIM, (long long)DDIM * HEDIM, (long long)CDIM * HEDIM,
        EDIM, (long long)HEDIM, EDIM);

    // K3: y_{b,e}[C,O] = h_{b,e}[C,HE] * w2_e
    moe_gemm<false, false, false>
        <<<dim3(ODIM / BN, CDIM / BM, BDIM * EDIM), THREADS, SMEM_TOTAL>>>(
        h, w2, y, nullptr,
        HEDIM, ODIM, ODIM, HEDIM / BK,
        (long long)CDIM * HEDIM, (long long)HEDIM * ODIM, (long long)CDIM * ODIM,
        EDIM, 0, 0);

    // K4: out_b[T,O] = comb_b[T,EC] * y_b[EC,O] + b2
    moe_gemm<false, false, true>
        <<<dim3(ODIM / BN, TDIM / BM, BDIM), THREADS, SMEM_TOTAL>>>(
        comb, y, out, b2,
        ECDIM, ODIM, ODIM, ECDIM / BK,
        (long long)TDIM * ECDIM, (long long)ECDIM * ODIM, (long long)TDIM * ODIM,
        0, 0, 1);
}